// round 5
// baseline (speedup 1.0000x reference)
#include <cuda_runtime.h>
#include <cuda_fp16.h>
#include <cstdint>

// Problem constants (fixed by setup_inputs)
#define Bb 4
#define Ts 4096
#define Dd 2560
#define Hh 10
#define BW 256
#define Mrows (Bb*Ts)   // 16384
#define NCHAN (Bb*Dd)   // 10240

// Scratch
__device__ float2 g_ax[(size_t)Bb * Ts * Dd];    // interleaved (a_eff, x_norm)
__device__ float  g_sp[Dd];                      // softplus(recurrent_param)
__device__ __align__(16) __half g_aH[(size_t)Mrows * Dd];      // fp16 copy of act
__device__ __align__(16) __half g_wH[(size_t)Hh * 512 * BW];   // fp16 interleaved K-major W

// chunked-scan partials
#define CH 128
#define NCH (Ts / CH)    // 32
__device__ float g_P[NCH * NCHAN];
__device__ float g_h[NCH * NCHAN];
__device__ float g_H[NCH * NCHAN];

// ---------------------------------------------------------------------------
__device__ __forceinline__ uint32_t smem_u32(const void* p) {
    uint32_t a;
    asm("{ .reg .u64 t; cvta.to.shared.u64 t, %1; cvt.u32.u64 %0, t; }" : "=r"(a) : "l"(p));
    return a;
}
__device__ __forceinline__ void mma_f16(float* c, const uint32_t* a, const uint32_t* b) {
    asm volatile("mma.sync.aligned.m16n8k16.row.col.f32.f16.f16.f32 "
                 "{%0,%1,%2,%3}, {%4,%5,%6,%7}, {%8,%9}, {%0,%1,%2,%3};"
                 : "+f"(c[0]), "+f"(c[1]), "+f"(c[2]), "+f"(c[3])
                 : "r"(a[0]), "r"(a[1]), "r"(a[2]), "r"(a[3]), "r"(b[0]), "r"(b[1]));
}
#define CPA(dst, src) asm volatile("cp.async.cg.shared.global [%0], [%1], 16;" \
                                   :: "r"(dst), "l"(src) : "memory")
#define CPC()  asm volatile("cp.async.commit_group;" ::: "memory")
#define CPW(n) asm volatile("cp.async.wait_group %0;" :: "n"(n) : "memory")

// ---------------------------------------------------------------------------
// Kernel 0: softplus table
// ---------------------------------------------------------------------------
__global__ void sp_kernel(const float* __restrict__ rp) {
    int d = blockIdx.x * blockDim.x + threadIdx.x;
    if (d < Dd) {
        float x = rp[d];
        g_sp[d] = (x > 20.0f) ? x : log1pf(__expf(x));
    }
}

// ---------------------------------------------------------------------------
// Kernel 0b: weight transpose+interleave+fp16: g_wH[h][2j+gate][k] = w_gate[h][k][j]
// ---------------------------------------------------------------------------
__global__ void wt_kernel(const float* __restrict__ wig, const float* __restrict__ wrg) {
    int idx = blockIdx.x * blockDim.x + threadIdx.x;   // Hh*512*256 total
    int k = idx & (BW - 1);
    int n = (idx >> 8) & 511;
    int h = idx >> 17;
    int j = n >> 1;
    const float* src = (n & 1) ? wrg : wig;
    g_wH[idx] = __float2half_rn(src[(size_t)h * BW * BW + (size_t)k * BW + j]);
}

// ---------------------------------------------------------------------------
// Kernel 0c: act fp32 -> fp16 copy
// ---------------------------------------------------------------------------
__global__ __launch_bounds__(256) void cvt_kernel(const float* __restrict__ act) {
    size_t i = ((size_t)blockIdx.x * 256 + threadIdx.x) * 4;
    float4 v = *(const float4*)(act + i);
    __half2* dst = (__half2*)(g_aH + i);
    dst[0] = __floats2half2_rn(v.x, v.y);
    dst[1] = __floats2half2_rn(v.z, v.w);
}

// ---------------------------------------------------------------------------
// Kernel 1: fp16 mma.sync m16n8k16 gates GEMM + fused epilogue, cp.async pipe.
// CTA: 128 rows x 256 interleaved-cols, K=256 in 4 tiles of 64 halfs.
// 8 warps 2(M) x 4(N); warp tile 64x64. smem pitch 72 halfs (conflict-free).
// ---------------------------------------------------------------------------
#define PH 72                               // halfs per smem row (144B)
#define A_B (128 * PH * 2)                  // 18432 B
#define W_B (256 * PH * 2)                  // 36864 B
#define STAGE_B (A_B + W_B)                 // 55296 B
#define SMEM_B (3 * STAGE_B)                // 165888 B

__global__ __launch_bounds__(256, 1) void gates_mma_kernel(
    const float* __restrict__ act, const int* __restrict__ pos,
    const float* __restrict__ big, const float* __restrict__ brg)
{
    extern __shared__ __half sm[];
    const uint32_t sbase = smem_u32(sm);

    const int tid = threadIdx.x;
    const int wid = tid >> 5, lane = tid & 31;
    const int g = lane >> 2, t = lane & 3;
    const int wm = wid & 1;        // 64-row slab
    const int wn = wid >> 1;       // 64-col slab
    const int h  = blockIdx.z;
    const int ny = blockIdx.y;     // N-half: j base ny*128
    const int rb = blockIdx.x * 128;

    const int sq = tid & 7;        // 16B chunk (8 halfs)
    const int sr = tid >> 3;       // 32 rows per pass

    const __half* aG = g_aH + (size_t)h * BW;
    const __half* wG = g_wH + ((size_t)h * 512 + ny * 256) * BW;

    float acc[4][8][4];
    #pragma unroll
    for (int mt = 0; mt < 4; mt++)
        #pragma unroll
        for (int nt = 0; nt < 8; nt++)
            #pragma unroll
            for (int c = 0; c < 4; c++) acc[mt][nt][c] = 0.0f;

    // issue one K-stage (64 halfs wide) into buffer `buf`
    auto issue = [&](int kt, int buf) {
        const int k0 = kt * 64;
        uint32_t Ad = sbase + buf * STAGE_B;
        uint32_t Wd = Ad + A_B;
        #pragma unroll
        for (int p = 0; p < 4; p++) {
            int r = sr + p * 32;
            CPA(Ad + r * (PH * 2) + sq * 16,
                aG + (size_t)(rb + r) * Dd + k0 + sq * 8);
        }
        #pragma unroll
        for (int p = 0; p < 8; p++) {
            int r = sr + p * 32;
            CPA(Wd + r * (PH * 2) + sq * 16,
                wG + (size_t)r * BW + k0 + sq * 8);
        }
    };

    issue(0, 0); CPC();
    issue(1, 1); CPC();

    #pragma unroll 1
    for (int kt = 0; kt < 4; kt++) {
        CPW(1);
        __syncthreads();
        const int buf = kt % 3;
        const __half* Ab = sm + buf * (STAGE_B / 2);
        const __half* Wb = Ab + (A_B / 2);

        #pragma unroll
        for (int k16 = 0; k16 < 4; k16++) {
            const int kk = k16 * 16 + 2 * t;     // even
            uint32_t bf[8][2];
            #pragma unroll
            for (int nt = 0; nt < 8; nt++) {
                int n = wn * 64 + nt * 8 + g;
                bf[nt][0] = *(const uint32_t*)&Wb[n * PH + kk];
                bf[nt][1] = *(const uint32_t*)&Wb[n * PH + kk + 8];
            }
            #pragma unroll
            for (int mt = 0; mt < 4; mt++) {
                int m = wm * 64 + mt * 16 + g;
                uint32_t af[4];
                af[0] = *(const uint32_t*)&Ab[m * PH + kk];
                af[1] = *(const uint32_t*)&Ab[(m + 8) * PH + kk];
                af[2] = *(const uint32_t*)&Ab[m * PH + kk + 8];
                af[3] = *(const uint32_t*)&Ab[(m + 8) * PH + kk + 8];
                #pragma unroll
                for (int nt = 0; nt < 8; nt++)
                    mma_f16(acc[mt][nt], af, bf[nt]);
            }
        }
        if (kt + 2 < 4) issue(kt + 2, (kt + 2) % 3);
        CPC();
    }

    // -------- fused epilogue (C layout identical to m16n8k8) --------
    float bi[8], br[8], sp8[8];
    const int dg0 = h * BW + ny * 128 + wn * 32 + t;
    #pragma unroll
    for (int nt = 0; nt < 8; nt++) {
        int dg = dg0 + nt * 4;
        bi[nt]  = big[dg];
        br[nt]  = brg[dg];
        sp8[nt] = g_sp[dg];
    }

    #pragma unroll
    for (int mt = 0; mt < 4; mt++) {
        int r1 = rb + wm * 64 + mt * 16 + g;
        int r2 = r1 + 8;
        bool rs1 = (pos[r1] == 0);
        bool rs2 = (pos[r2] == 0);
        const float* a1p = act + (size_t)r1 * Dd;
        const float* a2p = act + (size_t)r2 * Dd;
        float2* o1 = g_ax + (size_t)r1 * Dd;
        float2* o2 = g_ax + (size_t)r2 * Dd;
        #pragma unroll
        for (int nt = 0; nt < 8; nt++) {
            int dg = dg0 + nt * 4;
            {
                float ig = 1.0f / (1.0f + __expf(-(acc[mt][nt][0] + bi[nt])));
                float rg = 1.0f / (1.0f + __expf(-(acc[mt][nt][1] + br[nt])));
                float a  = __expf(-8.0f * rg * sp8[nt]);
                float m  = sqrtf(fmaxf(fmaf(-a, a, 1.0f), 0.0f));
                float xn = a1p[dg] * ig * (rs1 ? 1.0f : m);
                o1[dg] = make_float2(rs1 ? 0.0f : a, xn);
            }
            {
                float ig = 1.0f / (1.0f + __expf(-(acc[mt][nt][2] + bi[nt])));
                float rg = 1.0f / (1.0f + __expf(-(acc[mt][nt][3] + br[nt])));
                float a  = __expf(-8.0f * rg * sp8[nt]);
                float m  = sqrtf(fmaxf(fmaf(-a, a, 1.0f), 0.0f));
                float xn = a2p[dg] * ig * (rs2 ? 1.0f : m);
                o2[dg] = make_float2(rs2 ? 0.0f : a, xn);
            }
        }
    }
}

// ---------------------------------------------------------------------------
// Kernel 2a: per-chunk local scan -> (product, local final state)
// ---------------------------------------------------------------------------
__global__ __launch_bounds__(128) void scan_part_kernel() {
    int ch = blockIdx.x * 128 + threadIdx.x;
    int c  = blockIdx.y;
    int b  = ch / Dd;
    int d  = ch - b * Dd;
    size_t base = (size_t)b * Ts * Dd + (size_t)c * CH * Dd + d;

    float P = 1.0f, hacc = 0.0f;
    #pragma unroll 1
    for (int t0 = 0; t0 < CH; t0 += 8) {
        float2 v[8];
        #pragma unroll
        for (int u = 0; u < 8; u++) v[u] = g_ax[base + (size_t)(t0 + u) * Dd];
        #pragma unroll
        for (int u = 0; u < 8; u++) {
            P *= v[u].x;
            hacc = fmaf(v[u].x, hacc, v[u].y);
        }
    }
    g_P[c * NCHAN + ch] = P;
    g_h[c * NCHAN + ch] = hacc;
}

// ---------------------------------------------------------------------------
// Kernel 2b: cross-chunk recurrence (32 steps per channel, L2-resident)
// ---------------------------------------------------------------------------
__global__ __launch_bounds__(128) void scan_link_kernel() {
    int ch = blockIdx.x * 128 + threadIdx.x;
    float H = 0.0f;
    #pragma unroll
    for (int c = 0; c < NCH; c++) {
        g_H[c * NCHAN + ch] = H;
        H = fmaf(g_P[c * NCHAN + ch], H, g_h[c * NCHAN + ch]);
    }
}

// ---------------------------------------------------------------------------
// Kernel 2c: seeded local scan, write output
// ---------------------------------------------------------------------------
__global__ __launch_bounds__(128) void scan_final_kernel(float* __restrict__ out) {
    int ch = blockIdx.x * 128 + threadIdx.x;
    int c  = blockIdx.y;
    int b  = ch / Dd;
    int d  = ch - b * Dd;
    size_t base = (size_t)b * Ts * Dd + (size_t)c * CH * Dd + d;

    float hacc = g_H[c * NCHAN + ch];
    #pragma unroll 1
    for (int t0 = 0; t0 < CH; t0 += 8) {
        float2 v[8];
        #pragma unroll
        for (int u = 0; u < 8; u++) v[u] = g_ax[base + (size_t)(t0 + u) * Dd];
        #pragma unroll
        for (int u = 0; u < 8; u++) {
            hacc = fmaf(v[u].x, hacc, v[u].y);
            out[base + (size_t)(t0 + u) * Dd] = hacc;
        }
    }
}

// ---------------------------------------------------------------------------
extern "C" void kernel_launch(void* const* d_in, const int* in_sizes, int n_in,
                              void* d_out, int out_size) {
    const float* act = (const float*)d_in[0];
    const int*   pos = (const int*)  d_in[1];
    const float* wig = (const float*)d_in[2];
    const float* big = (const float*)d_in[3];
    const float* wrg = (const float*)d_in[4];
    const float* brg = (const float*)d_in[5];
    const float* rp  = (const float*)d_in[6];
    float* out = (float*)d_out;

    static int smem_set = 0;
    if (!smem_set) {
        cudaFuncSetAttribute(gates_mma_kernel,
                             cudaFuncAttributeMaxDynamicSharedMemorySize, SMEM_B);
        smem_set = 1;
    }

    sp_kernel<<<(Dd + 255) / 256, 256>>>(rp);
    wt_kernel<<<(Hh * 512 * BW) / 256, 256>>>(wig, wrg);
    cvt_kernel<<<((size_t)Mrows * Dd / 4) / 256, 256>>>(act);

    dim3 grid(Mrows / 128, 2, Hh);   // 2560 CTAs
    gates_mma_kernel<<<grid, 256, SMEM_B>>>(act, pos, big, brg);

    dim3 sgrid(NCHAN / 128, NCH);    // (80, 32)
    scan_part_kernel<<<sgrid, 128>>>();
    scan_link_kernel<<<NCHAN / 128, 128>>>();
    scan_final_kernel<<<sgrid, 128>>>(out);
}